// round 5
// baseline (speedup 1.0000x reference)
#include <cuda_runtime.h>
#include <cstdint>

#define D 64
#define NMAX 100000

// ---------------------------------------------------------------------------
// Device scratch
// ---------------------------------------------------------------------------
__device__ float4  g_hnew4[NMAX * (D / 4)];   // h_new accumulator (25.6 MB)
__device__ uint8_t g_Bimg[139264];            // bf16 hi (69632) + lo (69632) weight image
__device__ float   g_biasf[256];              // fused biases, col' = j*4+gate order
__device__ int     g_is32;                    // src/dst dtype flag

// SMEM map for the GEMM kernel
#define STRIDE_A 272            // 128 k * 2B padded to 17*16B (ldmatrix conflict-free)
#define A_HALF   34816          // 128 rows * 272
#define B_HALF   69632          // 256 rows * 272
#define SM_BIAS  0
#define SM_A     1024
#define SM_B     (SM_A + 2 * A_HALF)          // 70656
#define SM_TOT   (SM_B + 2 * B_HALF)          // 209920

// ---------------------------------------------------------------------------
// Helpers
// ---------------------------------------------------------------------------
__device__ __forceinline__ uint32_t smem_u32(const void* p) {
    uint32_t a;
    asm("{ .reg .u64 t; cvta.to.shared.u64 t, %1; cvt.u32.u64 %0, t; }"
        : "=r"(a) : "l"(p));
    return a;
}
__device__ __forceinline__ uint32_t cvtbf2(float hi, float lo) {
    uint32_t d;
    asm("cvt.rn.bf16x2.f32 %0, %1, %2;" : "=r"(d) : "f"(hi), "f"(lo));
    return d;
}
__device__ __forceinline__ float bflo_f(uint32_t p) { return __uint_as_float(p << 16); }
__device__ __forceinline__ float bfhi_f(uint32_t p) { return __uint_as_float(p & 0xffff0000u); }

__device__ __forceinline__ float sigmoidf_fast(float x) {
    return __fdividef(1.0f, 1.0f + __expf(-x));
}
__device__ __forceinline__ float tanhf_fast(float x) {
    return 1.0f - __fdividef(2.0f, __expf(2.0f * x) + 1.0f);
}

#define LDSM4(r0, r1, r2, r3, a)                                            \
    asm volatile("ldmatrix.sync.aligned.m8n8.x4.shared.b16 {%0,%1,%2,%3}, [%4];" \
                 : "=r"(r0), "=r"(r1), "=r"(r2), "=r"(r3) : "r"(a))

#define MMA16816(c, a0, a1, a2, a3, b0, b1)                                 \
    asm volatile("mma.sync.aligned.m16n8k16.row.col.f32.bf16.bf16.f32 "     \
                 "{%0,%1,%2,%3}, {%4,%5,%6,%7}, {%8,%9}, {%0,%1,%2,%3};"    \
                 : "+f"((c)[0]), "+f"((c)[1]), "+f"((c)[2]), "+f"((c)[3])   \
                 : "r"(a0), "r"(a1), "r"(a2), "r"(a3), "r"(b0), "r"(b1))

// ---------------------------------------------------------------------------
// Kernel 0: index dtype detection (int32 vs int64 node ids)
// ---------------------------------------------------------------------------
__global__ void detect_kernel(const unsigned long long* __restrict__ src,
                              const unsigned long long* __restrict__ dst) {
    if (threadIdx.x == 0 && blockIdx.x == 0) {
        unsigned long long acc = 0;
#pragma unroll
        for (int i = 0; i < 8; i++) acc |= (src[i] >> 32) | (dst[i] >> 32);
        g_is32 = (acc != 0ULL) ? 1 : 0;
    }
}

// ---------------------------------------------------------------------------
// Kernel 1: zero accumulator
// ---------------------------------------------------------------------------
__global__ void zero_kernel(int n4) {
    int i = blockIdx.x * blockDim.x + threadIdx.x;
    if (i < n4) g_hnew4[i] = make_float4(0.f, 0.f, 0.f, 0.f);
}

// ---------------------------------------------------------------------------
// Kernel 2: edge scatter via TMA bulk reduce.
// Each half-warp handles one edge: 16 lanes gather h[src] row (256B), scale
// by w, stage into a 4-deep SMEM slot ring; lane 0/16 issues one
// cp.reduce.async.bulk (f32 add at L2) for the whole 256B row.
// Removes the per-lane REDG issue cost that bound R4's scatter.
// ---------------------------------------------------------------------------
__global__ void __launch_bounds__(256)
scatter_kernel(const float4* __restrict__ h4,
               const float* __restrict__ ew,
               const void* __restrict__ srcp,
               const void* __restrict__ dstp,
               int E) {
    __shared__ __align__(16) float4 slots[8][4][2][16];   // 16 KB
    const int tid = threadIdx.x;
    const int w = tid >> 5, l = tid & 31;
    const int half = l >> 4, p = l & 15;
    const bool issuer = (p == 0);
    const bool is32 = (g_is32 != 0);
    const uint32_t sbase = smem_u32(&slots[w][0][0][0]);

    long long e0   = ((long long)blockIdx.x * 8 + w) * 2;
    const long long stride = (long long)gridDim.x * 8 * 2;
    int it = 0;

    for (; e0 < E; e0 += stride, it++) {
        const int stage = it & 3;
        if (issuer)
            asm volatile("cp.async.bulk.wait_group.read 3;" ::: "memory");
        __syncwarp();

        const long long e = e0 + half;
        const bool v = (e < E);
        int s = 0, d = 0;
        if (v) {
            if (is32) {
                s = ((const int*)srcp)[e];
                d = ((const int*)dstp)[e];
            } else {
                s = (int)((const long long*)srcp)[e];
                d = (int)((const long long*)dstp)[e];
            }
            const float wt = __ldg(&ew[e]);
            float4 hv = __ldg(&h4[(size_t)s * 16 + p]);
            hv.x *= wt; hv.y *= wt; hv.z *= wt; hv.w *= wt;
            slots[w][stage][half][p] = hv;
        }
        asm volatile("fence.proxy.async.shared::cta;" ::: "memory");
        __syncwarp();

        if (issuer) {
            if (v) {
                unsigned long long ga =
                    __cvta_generic_to_global((void*)&g_hnew4[(size_t)d * 16]);
                uint32_t sa = sbase + (uint32_t)(stage * 2 + half) * 256;
                asm volatile(
                    "cp.reduce.async.bulk.global.shared::cta.bulk_group.add.f32 "
                    "[%0], [%1], %2;"
                    :: "l"(ga), "r"(sa), "r"(256) : "memory");
            }
            asm volatile("cp.async.bulk.commit_group;" ::: "memory");
        }
    }
    if (issuer)
        asm volatile("cp.async.bulk.wait_group.read 0;" ::: "memory");
}

// ---------------------------------------------------------------------------
// Kernel 3: prep — bf16 hi/lo weight image + fused biases.
// B logical: [256 cols'][128 k], col' = j*4 + gate, k<64 -> x-part, k>=64 -> h-part.
// ---------------------------------------------------------------------------
__global__ void prep_kernel(const float* __restrict__ Wih,
                            const float* __restrict__ Whh,
                            const float* __restrict__ bih,
                            const float* __restrict__ bhh) {
    int idx = blockIdx.x * blockDim.x + threadIdx.x;   // 256 cols' x 32 quads
    if (idx < 8192) {
        int colp = idx >> 5, q = idx & 31;             // q: 4-k quad, q<16 -> x half
        int j = colp >> 2, g = colp & 3;
        int kk = (q & 15) * 4;                         // k within 64-half
        bool isX = (q < 16);
        float4 v = make_float4(0.f, 0.f, 0.f, 0.f);
        const float* srcRow = nullptr;
        if (g == 0)      srcRow = isX ? &Wih[j * 64]         : &Whh[j * 64];
        else if (g == 1) srcRow = isX ? &Wih[(64 + j) * 64]  : &Whh[(64 + j) * 64];
        else if (g == 2) srcRow = isX ? &Wih[(128 + j) * 64] : nullptr;
        else             srcRow = isX ? nullptr              : &Whh[(128 + j) * 64];
        if (srcRow) v = *(const float4*)(srcRow + kk);

        uint32_t h01 = cvtbf2(v.y, v.x), h23 = cvtbf2(v.w, v.z);
        uint32_t l01 = cvtbf2(v.y - bfhi_f(h01), v.x - bflo_f(h01));
        uint32_t l23 = cvtbf2(v.w - bfhi_f(h23), v.z - bflo_f(h23));
        uint32_t off = (uint32_t)colp * STRIDE_A + ((q >> 1) << 4) + ((q & 1) << 3);
        *(uint2*)(g_Bimg + off)          = make_uint2(h01, h23);
        *(uint2*)(g_Bimg + off + B_HALF) = make_uint2(l01, l23);
    }
    if (idx < 64) {
        g_biasf[idx * 4 + 0] = bih[idx] + bhh[idx];
        g_biasf[idx * 4 + 1] = bih[64 + idx] + bhh[64 + idx];
        g_biasf[idx * 4 + 2] = bih[128 + idx];
        g_biasf[idx * 4 + 3] = bhh[128 + idx];
    }
}

// ---------------------------------------------------------------------------
// Kernel 4: persistent bf16x3 mma.sync GEMM + fused GRU epilogue.
// CTA: 256 thr (8 warps). Warp tile: 16 m-rows x 256 n-cols. K=128.
// 3 passes: Ahi*Bhi + Ahi*Blo + Alo*Bhi into fp32 accum (128 regs/thread).
// ---------------------------------------------------------------------------
__global__ void __launch_bounds__(256, 1)
gemm_gru_kernel(const float4* __restrict__ h4, float* __restrict__ out,
                int Nn, int n_tiles) {
    extern __shared__ __align__(16) char smem[];
    const uint32_t sb = smem_u32(smem);
    const int tid = threadIdx.x;
    const int w = tid >> 5, l = tid & 31;
    const int gid = l >> 2, tg = l & 3;

    // --- B image + bias -> SMEM (linear, pre-formatted) ---
    {
        const uint4* srcB = (const uint4*)g_Bimg;
        uint4* dstB = (uint4*)(smem + SM_B);
        for (int i = tid; i < (2 * B_HALF) / 16; i += 256) dstB[i] = srcB[i];
        ((float*)smem)[tid] = g_biasf[tid];
    }
    __syncthreads();

    // ldmatrix lane address bases (272B row stride)
    const int sel = l >> 3;
    const uint32_t a_base = sb + SM_A +
        (uint32_t)((w * 16 + ((sel & 1) << 3) + (l & 7)) * STRIDE_A + ((sel >> 1) << 4));
    const uint32_t b_base = sb + SM_B +
        (uint32_t)((((sel >> 1) << 3) + (l & 7)) * STRIDE_A + ((sel & 1) << 4));

    const bool ev = !(l & 1);
    const int nodeloc = gid + (ev ? 0 : 8);

    for (int t = blockIdx.x; t < n_tiles; t += gridDim.x) {
        const int m0 = t << 7;

        // --- A tile: f32 -> bf16 hi/lo split, 272B-stride SMEM layout ---
#pragma unroll
        for (int it = 0; it < 16; it++) {
            int row = it * 8 + w;
            int node = m0 + row;
            int kq = l;                               // 4-k quad; <16: hnew, >=16: h
            float4 v = make_float4(0.f, 0.f, 0.f, 0.f);
            if (node < Nn)
                v = (kq < 16) ? g_hnew4[node * 16 + kq]
                              : __ldg(&h4[node * 16 + (kq - 16)]);
            uint32_t h01 = cvtbf2(v.y, v.x), h23 = cvtbf2(v.w, v.z);
            uint32_t l01 = cvtbf2(v.y - bfhi_f(h01), v.x - bflo_f(h01));
            uint32_t l23 = cvtbf2(v.w - bfhi_f(h23), v.z - bflo_f(h23));
            uint32_t off = (uint32_t)SM_A + (uint32_t)row * STRIDE_A +
                           ((uint32_t)(kq >> 1) << 4) + ((uint32_t)(kq & 1) << 3);
            *(uint2*)(smem + off)          = make_uint2(h01, h23);
            *(uint2*)(smem + off + A_HALF) = make_uint2(l01, l23);
        }
        __syncthreads();

        // --- GEMM: 3 split passes, 8 k-steps, 32 n-blocks ---
        float acc[128];
#pragma unroll
        for (int i = 0; i < 128; i++) acc[i] = 0.f;

#pragma unroll 1
        for (int p = 0; p < 3; p++) {
            const uint32_t ab = a_base + ((p == 2) ? (uint32_t)A_HALF : 0u);
            const uint32_t bb = b_base + ((p == 1) ? (uint32_t)B_HALF : 0u);
#pragma unroll
            for (int s = 0; s < 8; s++) {
                uint32_t a0, a1, a2, a3;
                LDSM4(a0, a1, a2, a3, ab + (uint32_t)s * 32);
#pragma unroll
                for (int nb = 0; nb < 16; nb++) {
                    uint32_t b0, b1, b2, b3;
                    LDSM4(b0, b1, b2, b3,
                          bb + (uint32_t)nb * (16 * STRIDE_A) + (uint32_t)s * 32);
                    MMA16816(&acc[(nb * 2) * 4],     a0, a1, a2, a3, b0, b1);
                    MMA16816(&acc[(nb * 2 + 1) * 4], a0, a1, a2, a3, b2, b3);
                }
            }
        }

        // --- Epilogue phase 1: gate math; output stashed into acc[fn*4] ---
        const int noderow = w * 16 + nodeloc;
#pragma unroll
        for (int fn = 0; fn < 32; fn++) {
            int jj = fn * 2 + (tg >> 1);
            float4 b4 = *(const float4*)(smem + SM_BIAS + jj * 16);
            float s0 = acc[fn * 4], s1 = acc[fn * 4 + 1];
            float s2 = acc[fn * 4 + 2], s3 = acc[fn * 4 + 3];
            float t0 = __shfl_xor_sync(0xffffffffu, s0, 1);
            float t1 = __shfl_xor_sync(0xffffffffu, s1, 1);
            float t2 = __shfl_xor_sync(0xffffffffu, s2, 1);
            float t3 = __shfl_xor_sync(0xffffffffu, s3, 1);
            float rs = ev ? s0 : t2;
            float zs = ev ? s1 : t3;
            float is = ev ? t0 : s2;
            float hs = ev ? t1 : s3;
            float r  = sigmoidf_fast(rs + b4.x);
            float z  = sigmoidf_fast(zs + b4.y);
            float nn = tanhf_fast(is + b4.z + r * (hs + b4.w));
            int kcol = 64 + jj;                 // h lives in A cols 64..127
            uint32_t hoff = (uint32_t)SM_A + (uint32_t)noderow * STRIDE_A +
                            ((uint32_t)(kcol >> 3) << 4) + ((uint32_t)(kcol & 7) << 1);
            uint32_t hib = *(const unsigned short*)(smem + hoff);
            uint32_t lob = *(const unsigned short*)(smem + hoff + A_HALF);
            float hv = __uint_as_float(hib << 16) + __uint_as_float(lob << 16);
            acc[fn * 4] = (1.f - z) * nn + z * hv;
        }
        __syncwarp();

        // --- Epilogue phase 2: stage into warp-local SMEM (XOR swizzle) ---
        const uint32_t stw = (uint32_t)SM_A + (uint32_t)w * (16 * STRIDE_A);
        const uint32_t pat = ((uint32_t)nodeloc & 7) << 5;
#pragma unroll
        for (int fn = 0; fn < 32; fn++) {
            int jj = fn * 2 + (tg >> 1);
            uint32_t sa = stw + (uint32_t)nodeloc * 256 + (((uint32_t)jj << 2) ^ pat);
            *(float*)(smem + sa) = acc[fn * 4];
        }
        __syncwarp();

        // --- Epilogue phase 3: coalesced 16B stores ---
#pragma unroll
        for (int it = 0; it < 8; it++) {
            int idx = it * 32 + l;
            int nl = idx >> 4, c16 = idx & 15;
            uint32_t ra = stw + (uint32_t)nl * 256 +
                          (((uint32_t)c16 << 4) ^ (((uint32_t)nl & 7) << 5));
            uint4 v = *(const uint4*)(smem + ra);
            int node = m0 + w * 16 + nl;
            if (node < Nn) *(uint4*)(out + (size_t)node * 64 + c16 * 4) = v;
        }
        __syncthreads();   // A region safe to rewrite next tile
    }
}

// ---------------------------------------------------------------------------
// Launch
// ---------------------------------------------------------------------------
extern "C" void kernel_launch(void* const* d_in, const int* in_sizes, int n_in,
                              void* d_out, int out_size) {
    const float* h   = (const float*)d_in[0];
    const float* ew  = (const float*)d_in[1];
    const float* Wih = (const float*)d_in[2];
    const float* Whh = (const float*)d_in[3];
    const float* bih = (const float*)d_in[4];
    const float* bhh = (const float*)d_in[5];
    const void* srcp = d_in[6];
    const void* dstp = d_in[7];
    float* out       = (float*)d_out;

    int E  = in_sizes[1];
    int Nn = in_sizes[0] / D;
    int n_tiles = (Nn + 127) / 128;

    detect_kernel<<<1, 32>>>((const unsigned long long*)srcp,
                             (const unsigned long long*)dstp);

    int n4 = Nn * (D / 4);
    zero_kernel<<<(n4 + 255) / 256, 256>>>(n4);

    prep_kernel<<<32, 256>>>(Wih, Whh, bih, bhh);

    scatter_kernel<<<1184, 256>>>((const float4*)h, ew, srcp, dstp, E);

    cudaFuncSetAttribute(gemm_gru_kernel,
                         cudaFuncAttributeMaxDynamicSharedMemorySize, SM_TOT);
    gemm_gru_kernel<<<148, 256, SM_TOT>>>((const float4*)h, out, Nn, n_tiles);
}

// round 6
// speedup vs baseline: 1.3038x; 1.3038x over previous
#include <cuda_runtime.h>
#include <cstdint>

#define D 64
#define NMAX 100000

// ---------------------------------------------------------------------------
// Device scratch
// ---------------------------------------------------------------------------
__device__ float4  g_hnew4[NMAX * (D / 4)];   // h_new accumulator (25.6 MB)
__device__ uint8_t g_Bimg[139264];            // bf16 hi (69632) + lo (69632) weight image
__device__ float   g_biasf[256];              // fused biases, col' = j*4+gate order
__device__ int     g_is32;                    // src/dst dtype flag

// SMEM map for the GEMM kernel
#define STRIDE_A 272            // 128 k * 2B padded to 17*16B (ldmatrix conflict-free)
#define A_HALF   34816          // 128 rows * 272
#define B_HALF   69632          // 256 rows * 272
#define SM_BIAS  0
#define SM_A     1024
#define SM_B     (SM_A + 2 * A_HALF)          // 70656
#define SM_TOT   (SM_B + 2 * B_HALF)          // 209920

// ---------------------------------------------------------------------------
// Helpers
// ---------------------------------------------------------------------------
__device__ __forceinline__ uint32_t smem_u32(const void* p) {
    uint32_t a;
    asm("{ .reg .u64 t; cvta.to.shared.u64 t, %1; cvt.u32.u64 %0, t; }"
        : "=r"(a) : "l"(p));
    return a;
}
__device__ __forceinline__ uint32_t cvtbf2(float hi, float lo) {
    uint32_t d;
    asm("cvt.rn.bf16x2.f32 %0, %1, %2;" : "=r"(d) : "f"(hi), "f"(lo));
    return d;
}
__device__ __forceinline__ float bflo_f(uint32_t p) { return __uint_as_float(p << 16); }
__device__ __forceinline__ float bfhi_f(uint32_t p) { return __uint_as_float(p & 0xffff0000u); }

__device__ __forceinline__ float sigmoidf_fast(float x) {
    return __fdividef(1.0f, 1.0f + __expf(-x));
}
__device__ __forceinline__ float tanhf_fast(float x) {
    return 1.0f - __fdividef(2.0f, __expf(2.0f * x) + 1.0f);
}

#define LDSM4(r0, r1, r2, r3, a)                                            \
    asm volatile("ldmatrix.sync.aligned.m8n8.x4.shared.b16 {%0,%1,%2,%3}, [%4];" \
                 : "=r"(r0), "=r"(r1), "=r"(r2), "=r"(r3) : "r"(a))

#define MMA16816(c, a0, a1, a2, a3, b0, b1)                                 \
    asm volatile("mma.sync.aligned.m16n8k16.row.col.f32.bf16.bf16.f32 "     \
                 "{%0,%1,%2,%3}, {%4,%5,%6,%7}, {%8,%9}, {%0,%1,%2,%3};"    \
                 : "+f"((c)[0]), "+f"((c)[1]), "+f"((c)[2]), "+f"((c)[3])   \
                 : "r"(a0), "r"(a1), "r"(a2), "r"(a3), "r"(b0), "r"(b1))

// ---------------------------------------------------------------------------
// Kernel 0: index dtype detection (int32 vs int64 node ids)
// ---------------------------------------------------------------------------
__global__ void detect_kernel(const unsigned long long* __restrict__ src,
                              const unsigned long long* __restrict__ dst) {
    if (threadIdx.x == 0 && blockIdx.x == 0) {
        unsigned long long acc = 0;
#pragma unroll
        for (int i = 0; i < 8; i++) acc |= (src[i] >> 32) | (dst[i] >> 32);
        g_is32 = (acc != 0ULL) ? 1 : 0;
    }
}

// ---------------------------------------------------------------------------
// Kernel 1: zero accumulator
// ---------------------------------------------------------------------------
__global__ void zero_kernel(int n4) {
    int i = blockIdx.x * blockDim.x + threadIdx.x;
    if (i < n4) g_hnew4[i] = make_float4(0.f, 0.f, 0.f, 0.f);
}

// ---------------------------------------------------------------------------
// Kernel 2: edge scatter, 4-edge batched. 16 threads cover an edge row part p;
// each thread handles the same part p of 4 consecutive edges: phase 1 loads
// all 4 index/weight triples, phase 2 issues 4 independent gathers, phase 3
// issues 4 RED.v4 — MLP=4 hides the idx->gather->reduce latency chain that
// bound R4's one-edge-per-thread version.
// ---------------------------------------------------------------------------
__global__ void __launch_bounds__(256)
scatter_kernel(const float4* __restrict__ h4,
               const float* __restrict__ ew,
               const void* __restrict__ srcp,
               const void* __restrict__ dstp,
               int E) {
    const int gid = blockIdx.x * blockDim.x + threadIdx.x;
    const int p = gid & 15;
    const long long g = (long long)(gid >> 4) * 4;     // first edge of batch
    if (g >= E) return;
    const bool is32 = (g_is32 != 0);

    int s[4], d[4];
    float wt[4];
    int nv = 0;
#pragma unroll
    for (int b = 0; b < 4; b++) {
        long long e = g + b;
        if (e < E) {
            if (is32) {
                s[b] = ((const int*)srcp)[e];
                d[b] = ((const int*)dstp)[e];
            } else {
                s[b] = (int)((const long long*)srcp)[e];
                d[b] = (int)((const long long*)dstp)[e];
            }
            wt[b] = __ldg(&ew[e]);
            nv = b + 1;
        }
    }

    float4 v[4];
#pragma unroll
    for (int b = 0; b < 4; b++)
        if (b < nv) v[b] = __ldg(&h4[(size_t)s[b] * 16 + p]);

#pragma unroll
    for (int b = 0; b < 4; b++) {
        if (b < nv) {
            float4 u = v[b];
            float w = wt[b];
            u.x *= w; u.y *= w; u.z *= w; u.w *= w;
            unsigned long long gptr =
                __cvta_generic_to_global((void*)&g_hnew4[(size_t)d[b] * 16 + p]);
            asm volatile("red.global.add.v4.f32 [%0], {%1, %2, %3, %4};"
                         :: "l"(gptr), "f"(u.x), "f"(u.y), "f"(u.z), "f"(u.w)
                         : "memory");
        }
    }
}

// ---------------------------------------------------------------------------
// Kernel 3: prep — bf16 hi/lo weight image + fused biases.
// B logical: [256 cols'][128 k], col' = j*4 + gate, k<64 -> x-part, k>=64 -> h-part.
// ---------------------------------------------------------------------------
__global__ void prep_kernel(const float* __restrict__ Wih,
                            const float* __restrict__ Whh,
                            const float* __restrict__ bih,
                            const float* __restrict__ bhh) {
    int idx = blockIdx.x * blockDim.x + threadIdx.x;   // 256 cols' x 32 quads
    if (idx < 8192) {
        int colp = idx >> 5, q = idx & 31;             // q: 4-k quad, q<16 -> x half
        int j = colp >> 2, g = colp & 3;
        int kk = (q & 15) * 4;                         // k within 64-half
        bool isX = (q < 16);
        float4 v = make_float4(0.f, 0.f, 0.f, 0.f);
        const float* srcRow = nullptr;
        if (g == 0)      srcRow = isX ? &Wih[j * 64]         : &Whh[j * 64];
        else if (g == 1) srcRow = isX ? &Wih[(64 + j) * 64]  : &Whh[(64 + j) * 64];
        else if (g == 2) srcRow = isX ? &Wih[(128 + j) * 64] : nullptr;
        else             srcRow = isX ? nullptr              : &Whh[(128 + j) * 64];
        if (srcRow) v = *(const float4*)(srcRow + kk);

        uint32_t h01 = cvtbf2(v.y, v.x), h23 = cvtbf2(v.w, v.z);
        uint32_t l01 = cvtbf2(v.y - bfhi_f(h01), v.x - bflo_f(h01));
        uint32_t l23 = cvtbf2(v.w - bfhi_f(h23), v.z - bflo_f(h23));
        uint32_t off = (uint32_t)colp * STRIDE_A + ((q >> 1) << 4) + ((q & 1) << 3);
        *(uint2*)(g_Bimg + off)          = make_uint2(h01, h23);
        *(uint2*)(g_Bimg + off + B_HALF) = make_uint2(l01, l23);
    }
    if (idx < 64) {
        g_biasf[idx * 4 + 0] = bih[idx] + bhh[idx];
        g_biasf[idx * 4 + 1] = bih[64 + idx] + bhh[64 + idx];
        g_biasf[idx * 4 + 2] = bih[128 + idx];
        g_biasf[idx * 4 + 3] = bhh[128 + idx];
    }
}

// ---------------------------------------------------------------------------
// Kernel 4: persistent bf16x3 mma.sync GEMM + fused GRU epilogue.
// Fused single-loop split: per k-step LDSM A-hi+A-lo; per n-block LDSM
// B-hi+B-lo serving 6 MMAs (hi*hi, hi*lo, lo*hi). 272 LDSM vs 408 in the
// 3-pass form, and one flat loop for ptxas to software-pipeline.
// ---------------------------------------------------------------------------
__global__ void __launch_bounds__(256, 1)
gemm_gru_kernel(const float4* __restrict__ h4, float* __restrict__ out,
                int Nn, int n_tiles) {
    extern __shared__ __align__(16) char smem[];
    const uint32_t sb = smem_u32(smem);
    const int tid = threadIdx.x;
    const int w = tid >> 5, l = tid & 31;
    const int gid = l >> 2, tg = l & 3;

    // --- B image + bias -> SMEM (linear, pre-formatted) ---
    {
        const uint4* srcB = (const uint4*)g_Bimg;
        uint4* dstB = (uint4*)(smem + SM_B);
        for (int i = tid; i < (2 * B_HALF) / 16; i += 256) dstB[i] = srcB[i];
        ((float*)smem)[tid] = g_biasf[tid];
    }
    __syncthreads();

    // ldmatrix lane address bases (272B row stride)
    const int sel = l >> 3;
    const uint32_t a_base = sb + SM_A +
        (uint32_t)((w * 16 + ((sel & 1) << 3) + (l & 7)) * STRIDE_A + ((sel >> 1) << 4));
    const uint32_t b_base = sb + SM_B +
        (uint32_t)((((sel >> 1) << 3) + (l & 7)) * STRIDE_A + ((sel & 1) << 4));

    const bool ev = !(l & 1);
    const int nodeloc = gid + (ev ? 0 : 8);

    for (int t = blockIdx.x; t < n_tiles; t += gridDim.x) {
        const int m0 = t << 7;

        // --- A tile: f32 -> bf16 hi/lo split, 272B-stride SMEM layout ---
#pragma unroll
        for (int it = 0; it < 16; it++) {
            int row = it * 8 + w;
            int node = m0 + row;
            int kq = l;                               // 4-k quad; <16: hnew, >=16: h
            float4 v = make_float4(0.f, 0.f, 0.f, 0.f);
            if (node < Nn)
                v = (kq < 16) ? g_hnew4[node * 16 + kq]
                              : __ldg(&h4[node * 16 + (kq - 16)]);
            uint32_t h01 = cvtbf2(v.y, v.x), h23 = cvtbf2(v.w, v.z);
            uint32_t l01 = cvtbf2(v.y - bfhi_f(h01), v.x - bflo_f(h01));
            uint32_t l23 = cvtbf2(v.w - bfhi_f(h23), v.z - bflo_f(h23));
            uint32_t off = (uint32_t)SM_A + (uint32_t)row * STRIDE_A +
                           ((uint32_t)(kq >> 1) << 4) + ((uint32_t)(kq & 1) << 3);
            *(uint2*)(smem + off)          = make_uint2(h01, h23);
            *(uint2*)(smem + off + A_HALF) = make_uint2(l01, l23);
        }
        __syncthreads();

        // --- GEMM: fused split, 8 k-steps x 16 n-blocks x 6 MMAs ---
        float acc[128];
#pragma unroll
        for (int i = 0; i < 128; i++) acc[i] = 0.f;

#pragma unroll 2
        for (int s = 0; s < 8; s++) {
            uint32_t ah0, ah1, ah2, ah3, al0, al1, al2, al3;
            LDSM4(ah0, ah1, ah2, ah3, a_base + (uint32_t)s * 32);
            LDSM4(al0, al1, al2, al3, a_base + A_HALF + (uint32_t)s * 32);
#pragma unroll
            for (int nb = 0; nb < 16; nb++) {
                const uint32_t bb = b_base + (uint32_t)nb * (16 * STRIDE_A) +
                                    (uint32_t)s * 32;
                uint32_t bh0, bh1, bh2, bh3, bl0, bl1, bl2, bl3;
                LDSM4(bh0, bh1, bh2, bh3, bb);
                LDSM4(bl0, bl1, bl2, bl3, bb + B_HALF);
                float* c0 = &acc[(nb * 2) * 4];
                float* c1 = &acc[(nb * 2 + 1) * 4];
                MMA16816(c0, ah0, ah1, ah2, ah3, bh0, bh1);
                MMA16816(c1, ah0, ah1, ah2, ah3, bh2, bh3);
                MMA16816(c0, ah0, ah1, ah2, ah3, bl0, bl1);
                MMA16816(c1, ah0, ah1, ah2, ah3, bl2, bl3);
                MMA16816(c0, al0, al1, al2, al3, bh0, bh1);
                MMA16816(c1, al0, al1, al2, al3, bh2, bh3);
            }
        }

        // --- Epilogue phase 1: gate math; output stashed into acc[fn*4] ---
        const int noderow = w * 16 + nodeloc;
#pragma unroll
        for (int fn = 0; fn < 32; fn++) {
            int jj = fn * 2 + (tg >> 1);
            float4 b4 = *(const float4*)(smem + SM_BIAS + jj * 16);
            float s0 = acc[fn * 4], s1 = acc[fn * 4 + 1];
            float s2 = acc[fn * 4 + 2], s3 = acc[fn * 4 + 3];
            float t0 = __shfl_xor_sync(0xffffffffu, s0, 1);
            float t1 = __shfl_xor_sync(0xffffffffu, s1, 1);
            float t2 = __shfl_xor_sync(0xffffffffu, s2, 1);
            float t3 = __shfl_xor_sync(0xffffffffu, s3, 1);
            float rs = ev ? s0 : t2;
            float zs = ev ? s1 : t3;
            float is = ev ? t0 : s2;
            float hs = ev ? t1 : s3;
            float r  = sigmoidf_fast(rs + b4.x);
            float z  = sigmoidf_fast(zs + b4.y);
            float nn = tanhf_fast(is + b4.z + r * (hs + b4.w));
            int kcol = 64 + jj;                 // h lives in A cols 64..127
            uint32_t hoff = (uint32_t)SM_A + (uint32_t)noderow * STRIDE_A +
                            ((uint32_t)(kcol >> 3) << 4) + ((uint32_t)(kcol & 7) << 1);
            uint32_t hib = *(const unsigned short*)(smem + hoff);
            uint32_t lob = *(const unsigned short*)(smem + hoff + A_HALF);
            float hv = __uint_as_float(hib << 16) + __uint_as_float(lob << 16);
            acc[fn * 4] = (1.f - z) * nn + z * hv;
        }
        __syncwarp();

        // --- Epilogue phase 2: stage into warp-local SMEM (XOR swizzle) ---
        const uint32_t stw = (uint32_t)SM_A + (uint32_t)w * (16 * STRIDE_A);
        const uint32_t pat = ((uint32_t)nodeloc & 7) << 5;
#pragma unroll
        for (int fn = 0; fn < 32; fn++) {
            int jj = fn * 2 + (tg >> 1);
            uint32_t sa = stw + (uint32_t)nodeloc * 256 + (((uint32_t)jj << 2) ^ pat);
            *(float*)(smem + sa) = acc[fn * 4];
        }
        __syncwarp();

        // --- Epilogue phase 3: coalesced 16B stores ---
#pragma unroll
        for (int it = 0; it < 8; it++) {
            int idx = it * 32 + l;
            int nl = idx >> 4, c16 = idx & 15;
            uint32_t ra = stw + (uint32_t)nl * 256 +
                          (((uint32_t)c16 << 4) ^ (((uint32_t)nl & 7) << 5));
            uint4 v = *(const uint4*)(smem + ra);
            int node = m0 + w * 16 + nl;
            if (node < Nn) *(uint4*)(out + (size_t)node * 64 + c16 * 4) = v;
        }
        __syncthreads();   // A region safe to rewrite next tile
    }
}

// ---------------------------------------------------------------------------
// Launch
// ---------------------------------------------------------------------------
extern "C" void kernel_launch(void* const* d_in, const int* in_sizes, int n_in,
                              void* d_out, int out_size) {
    const float* h   = (const float*)d_in[0];
    const float* ew  = (const float*)d_in[1];
    const float* Wih = (const float*)d_in[2];
    const float* Whh = (const float*)d_in[3];
    const float* bih = (const float*)d_in[4];
    const float* bhh = (const float*)d_in[5];
    const void* srcp = d_in[6];
    const void* dstp = d_in[7];
    float* out       = (float*)d_out;

    int E  = in_sizes[1];
    int Nn = in_sizes[0] / D;
    int n_tiles = (Nn + 127) / 128;

    detect_kernel<<<1, 32>>>((const unsigned long long*)srcp,
                             (const unsigned long long*)dstp);

    int n4 = Nn * (D / 4);
    zero_kernel<<<(n4 + 255) / 256, 256>>>(n4);

    prep_kernel<<<32, 256>>>(Wih, Whh, bih, bhh);

    // 4 edges per thread batch: threads = ceil(E/4)*16
    long long sthreads = (long long)((E + 3) / 4) * 16;
    int sblocks = (int)((sthreads + 255) / 256);
    scatter_kernel<<<sblocks, 256>>>((const float4*)h, ew, srcp, dstp, E);

    cudaFuncSetAttribute(gemm_gru_kernel,
                         cudaFuncAttributeMaxDynamicSharedMemorySize, SM_TOT);
    gemm_gru_kernel<<<148, 256, SM_TOT>>>((const float4*)h, out, Nn, n_tiles);
}

// round 7
// speedup vs baseline: 1.8646x; 1.4301x over previous
#include <cuda_runtime.h>
#include <cstdint>

#define D 64
#define NMAX 100000

// ---------------------------------------------------------------------------
// Device scratch
// ---------------------------------------------------------------------------
__device__ float4  g_hnew4[NMAX * (D / 4)];   // h_new accumulator (25.6 MB)
__device__ uint8_t g_Bimg[139264];            // bf16 hi (69632) + lo (69632) weight image
__device__ float   g_biasf[256];              // fused biases, col' = j*4+gate order
__device__ int     g_is32;                    // src/dst dtype flag

// SMEM map for the GEMM kernel
#define STRIDE_A 272            // 128 k * 2B padded to 17*16B (ldmatrix conflict-free)
#define A_HALF_W 4352           // per-warp A half: 16 rows * 272
#define A_WARP   8704           // per-warp A region (hi + lo)
#define B_HALF   69632          // 256 rows * 272
#define SM_BIAS  0
#define SM_A     1024
#define SM_B     (SM_A + 8 * A_WARP)          // 70656
#define SM_TOT   (SM_B + 2 * B_HALF)          // 209920

// ---------------------------------------------------------------------------
// Helpers
// ---------------------------------------------------------------------------
__device__ __forceinline__ uint32_t smem_u32(const void* p) {
    uint32_t a;
    asm("{ .reg .u64 t; cvta.to.shared.u64 t, %1; cvt.u32.u64 %0, t; }"
        : "=r"(a) : "l"(p));
    return a;
}
__device__ __forceinline__ uint32_t cvtbf2(float hi, float lo) {
    uint32_t d;
    asm("cvt.rn.bf16x2.f32 %0, %1, %2;" : "=r"(d) : "f"(hi), "f"(lo));
    return d;
}
__device__ __forceinline__ float bflo_f(uint32_t p) { return __uint_as_float(p << 16); }
__device__ __forceinline__ float bfhi_f(uint32_t p) { return __uint_as_float(p & 0xffff0000u); }

__device__ __forceinline__ float sigmoidf_fast(float x) {
    return __fdividef(1.0f, 1.0f + __expf(-x));
}
__device__ __forceinline__ float tanhf_fast(float x) {
    return 1.0f - __fdividef(2.0f, __expf(2.0f * x) + 1.0f);
}

#define LDSM4(r0, r1, r2, r3, a)                                            \
    asm volatile("ldmatrix.sync.aligned.m8n8.x4.shared.b16 {%0,%1,%2,%3}, [%4];" \
                 : "=r"(r0), "=r"(r1), "=r"(r2), "=r"(r3) : "r"(a))

#define MMA16816(c, a0, a1, a2, a3, b0, b1)                                 \
    asm volatile("mma.sync.aligned.m16n8k16.row.col.f32.bf16.bf16.f32 "     \
                 "{%0,%1,%2,%3}, {%4,%5,%6,%7}, {%8,%9}, {%0,%1,%2,%3};"    \
                 : "+f"((c)[0]), "+f"((c)[1]), "+f"((c)[2]), "+f"((c)[3])   \
                 : "r"(a0), "r"(a1), "r"(a2), "r"(a3), "r"(b0), "r"(b1))

// ---------------------------------------------------------------------------
// Kernel 0: index dtype detection (int32 vs int64 node ids)
// ---------------------------------------------------------------------------
__global__ void detect_kernel(const unsigned long long* __restrict__ src,
                              const unsigned long long* __restrict__ dst) {
    if (threadIdx.x == 0 && blockIdx.x == 0) {
        unsigned long long acc = 0;
#pragma unroll
        for (int i = 0; i < 8; i++) acc |= (src[i] >> 32) | (dst[i] >> 32);
        g_is32 = (acc != 0ULL) ? 1 : 0;
    }
}

// ---------------------------------------------------------------------------
// Kernel 1: zero accumulator
// ---------------------------------------------------------------------------
__global__ void zero_kernel(int n4) {
    int i = blockIdx.x * blockDim.x + threadIdx.x;
    if (i < n4) g_hnew4[i] = make_float4(0.f, 0.f, 0.f, 0.f);
}

// ---------------------------------------------------------------------------
// Kernel 2: edge scatter (R4 form — one edge per 16 threads, RED.v4).
// This sits at the REDG per-lane floor (~1 cyc/lane); leave it alone.
// ---------------------------------------------------------------------------
__global__ void scatter_kernel(const float4* __restrict__ h4,
                               const float* __restrict__ ew,
                               const void* __restrict__ srcp,
                               const void* __restrict__ dstp,
                               int E) {
    int gid = blockIdx.x * blockDim.x + threadIdx.x;
    int e = gid >> 4;
    int p = gid & 15;
    if (e >= E) return;
    int s, d;
    if (g_is32) {
        s = ((const int*)srcp)[e];
        d = ((const int*)dstp)[e];
    } else {
        s = (int)((const long long*)srcp)[e];
        d = (int)((const long long*)dstp)[e];
    }
    float w = ew[e];
    float4 v = __ldg(&h4[s * 16 + p]);
    v.x *= w; v.y *= w; v.z *= w; v.w *= w;
    unsigned long long gptr = __cvta_generic_to_global((void*)&g_hnew4[d * 16 + p]);
    asm volatile("red.global.add.v4.f32 [%0], {%1, %2, %3, %4};"
                 :: "l"(gptr), "f"(v.x), "f"(v.y), "f"(v.z), "f"(v.w) : "memory");
}

// ---------------------------------------------------------------------------
// Kernel 3: prep — bf16 hi/lo weight image + fused biases.
// B logical: [256 cols'][128 k], col' = j*4 + gate, k<64 -> x-part, k>=64 -> h-part.
// ---------------------------------------------------------------------------
__global__ void prep_kernel(const float* __restrict__ Wih,
                            const float* __restrict__ Whh,
                            const float* __restrict__ bih,
                            const float* __restrict__ bhh) {
    int idx = blockIdx.x * blockDim.x + threadIdx.x;   // 256 cols' x 32 quads
    if (idx < 8192) {
        int colp = idx >> 5, q = idx & 31;             // q: 4-k quad, q<16 -> x half
        int j = colp >> 2, g = colp & 3;
        int kk = (q & 15) * 4;                         // k within 64-half
        bool isX = (q < 16);
        float4 v = make_float4(0.f, 0.f, 0.f, 0.f);
        const float* srcRow = nullptr;
        if (g == 0)      srcRow = isX ? &Wih[j * 64]         : &Whh[j * 64];
        else if (g == 1) srcRow = isX ? &Wih[(64 + j) * 64]  : &Whh[(64 + j) * 64];
        else if (g == 2) srcRow = isX ? &Wih[(128 + j) * 64] : nullptr;
        else             srcRow = isX ? nullptr              : &Whh[(128 + j) * 64];
        if (srcRow) v = *(const float4*)(srcRow + kk);

        uint32_t h01 = cvtbf2(v.y, v.x), h23 = cvtbf2(v.w, v.z);
        uint32_t l01 = cvtbf2(v.y - bfhi_f(h01), v.x - bflo_f(h01));
        uint32_t l23 = cvtbf2(v.w - bfhi_f(h23), v.z - bflo_f(h23));
        uint32_t off = (uint32_t)colp * STRIDE_A + ((q >> 1) << 4) + ((q & 1) << 3);
        *(uint2*)(g_Bimg + off)          = make_uint2(h01, h23);
        *(uint2*)(g_Bimg + off + B_HALF) = make_uint2(l01, l23);
    }
    if (idx < 64) {
        g_biasf[idx * 4 + 0] = bih[idx] + bhh[idx];
        g_biasf[idx * 4 + 1] = bih[64 + idx] + bhh[64 + idx];
        g_biasf[idx * 4 + 2] = bih[128 + idx];
        g_biasf[idx * 4 + 3] = bhh[128 + idx];
    }
}

// ---------------------------------------------------------------------------
// Kernel 4: bf16x3 mma.sync GEMM + GRU epilogue, WARP-INDEPENDENT tiles.
// Each warp owns a private 16-row A slice (hi+lo) and grid-strides over
// 16-node tiles with NO CTA barriers in the loop — epilogue/A-prep of one
// warp overlaps MMA of the other warp on the same SMSP.
// Inner GEMM is the proven R4 3-pass form (no spills).
// ---------------------------------------------------------------------------
__global__ void __launch_bounds__(256, 1)
gemm_gru_kernel(const float4* __restrict__ h4, float* __restrict__ out,
                int Nn, int n_tiles16) {
    extern __shared__ __align__(16) char smem[];
    const uint32_t sb = smem_u32(smem);
    const int tid = threadIdx.x;
    const int w = tid >> 5, l = tid & 31;
    const int gid = l >> 2, tg = l & 3;

    // --- B image + bias -> SMEM (linear, pre-formatted) ---
    {
        const uint4* srcB = (const uint4*)g_Bimg;
        uint4* dstB = (uint4*)(smem + SM_B);
        for (int i = tid; i < (2 * B_HALF) / 16; i += 256) dstB[i] = srcB[i];
        ((float*)smem)[tid] = g_biasf[tid];
    }
    __syncthreads();

    const int warpA_off = SM_A + w * A_WARP;           // warp-private A region
    const int sel = l >> 3;
    const uint32_t a_base = sb + (uint32_t)warpA_off +
        (uint32_t)((((sel & 1) << 3) + (l & 7)) * STRIDE_A + ((sel >> 1) << 4));
    const uint32_t b_base = sb + SM_B +
        (uint32_t)((((sel >> 1) << 3) + (l & 7)) * STRIDE_A + ((sel & 1) << 4));

    const bool ev = !(l & 1);
    const int nodeloc = gid + (ev ? 0 : 8);

    for (int tw = blockIdx.x * 8 + w; tw < n_tiles16; tw += gridDim.x * 8) {
        const int m0 = tw << 4;

        // --- A tile (16 rows, warp-private): f32 -> bf16 hi/lo split ---
#pragma unroll
        for (int it = 0; it < 16; it++) {
            int node = m0 + it;
            int kq = l;                               // 4-k quad; <16: hnew, >=16: h
            float4 v = make_float4(0.f, 0.f, 0.f, 0.f);
            if (node < Nn)
                v = (kq < 16) ? g_hnew4[node * 16 + kq]
                              : __ldg(&h4[node * 16 + (kq - 16)]);
            uint32_t h01 = cvtbf2(v.y, v.x), h23 = cvtbf2(v.w, v.z);
            uint32_t l01 = cvtbf2(v.y - bfhi_f(h01), v.x - bflo_f(h01));
            uint32_t l23 = cvtbf2(v.w - bfhi_f(h23), v.z - bflo_f(h23));
            uint32_t off = (uint32_t)warpA_off + (uint32_t)it * STRIDE_A +
                           ((uint32_t)(kq >> 1) << 4) + ((uint32_t)(kq & 1) << 3);
            *(uint2*)(smem + off)            = make_uint2(h01, h23);
            *(uint2*)(smem + off + A_HALF_W) = make_uint2(l01, l23);
        }
        __syncwarp();

        // --- GEMM: 3 split passes, 8 k-steps, 32 n-blocks (R4 form) ---
        float acc[128];
#pragma unroll
        for (int i = 0; i < 128; i++) acc[i] = 0.f;

#pragma unroll 1
        for (int p = 0; p < 3; p++) {
            const uint32_t ab = a_base + ((p == 2) ? (uint32_t)A_HALF_W : 0u);
            const uint32_t bb = b_base + ((p == 1) ? (uint32_t)B_HALF : 0u);
#pragma unroll
            for (int s = 0; s < 8; s++) {
                uint32_t a0, a1, a2, a3;
                LDSM4(a0, a1, a2, a3, ab + (uint32_t)s * 32);
#pragma unroll
                for (int nb = 0; nb < 16; nb++) {
                    uint32_t b0, b1, b2, b3;
                    LDSM4(b0, b1, b2, b3,
                          bb + (uint32_t)nb * (16 * STRIDE_A) + (uint32_t)s * 32);
                    MMA16816(&acc[(nb * 2) * 4],     a0, a1, a2, a3, b0, b1);
                    MMA16816(&acc[(nb * 2 + 1) * 4], a0, a1, a2, a3, b2, b3);
                }
            }
        }

        // --- Epilogue phase 1: gate math; output stashed into acc[fn*4] ---
#pragma unroll
        for (int fn = 0; fn < 32; fn++) {
            int jj = fn * 2 + (tg >> 1);
            float4 b4 = *(const float4*)(smem + SM_BIAS + jj * 16);
            float s0 = acc[fn * 4], s1 = acc[fn * 4 + 1];
            float s2 = acc[fn * 4 + 2], s3 = acc[fn * 4 + 3];
            float t0 = __shfl_xor_sync(0xffffffffu, s0, 1);
            float t1 = __shfl_xor_sync(0xffffffffu, s1, 1);
            float t2 = __shfl_xor_sync(0xffffffffu, s2, 1);
            float t3 = __shfl_xor_sync(0xffffffffu, s3, 1);
            float rs = ev ? s0 : t2;
            float zs = ev ? s1 : t3;
            float is = ev ? t0 : s2;
            float hs = ev ? t1 : s3;
            float r  = sigmoidf_fast(rs + b4.x);
            float z  = sigmoidf_fast(zs + b4.y);
            float nn = tanhf_fast(is + b4.z + r * (hs + b4.w));
            int kcol = 64 + jj;                 // h lives in A cols 64..127
            uint32_t hoff = (uint32_t)warpA_off + (uint32_t)nodeloc * STRIDE_A +
                            ((uint32_t)(kcol >> 3) << 4) + ((uint32_t)(kcol & 7) << 1);
            uint32_t hib = *(const unsigned short*)(smem + hoff);
            uint32_t lob = *(const unsigned short*)(smem + hoff + A_HALF_W);
            float hv = __uint_as_float(hib << 16) + __uint_as_float(lob << 16);
            acc[fn * 4] = (1.f - z) * nn + z * hv;
        }
        __syncwarp();

        // --- Epilogue phase 2: stage into warp-private SMEM (XOR swizzle) ---
        const uint32_t pat = ((uint32_t)nodeloc & 7) << 5;
#pragma unroll
        for (int fn = 0; fn < 32; fn++) {
            int jj = fn * 2 + (tg >> 1);
            uint32_t sa = (uint32_t)warpA_off + (uint32_t)nodeloc * 256 +
                          (((uint32_t)jj << 2) ^ pat);
            *(float*)(smem + sa) = acc[fn * 4];
        }
        __syncwarp();

        // --- Epilogue phase 3: coalesced 16B stores ---
#pragma unroll
        for (int it = 0; it < 8; it++) {
            int idx = it * 32 + l;
            int nl = idx >> 4, c16 = idx & 15;
            uint32_t ra = (uint32_t)warpA_off + (uint32_t)nl * 256 +
                          (((uint32_t)c16 << 4) ^ (((uint32_t)nl & 7) << 5));
            uint4 v = *(const uint4*)(smem + ra);
            int node = m0 + nl;
            if (node < Nn) *(uint4*)(out + (size_t)node * 64 + c16 * 4) = v;
        }
        __syncwarp();   // staging/A safe to rewrite next tile
    }
}

// ---------------------------------------------------------------------------
// Launch
// ---------------------------------------------------------------------------
extern "C" void kernel_launch(void* const* d_in, const int* in_sizes, int n_in,
                              void* d_out, int out_size) {
    const float* h   = (const float*)d_in[0];
    const float* ew  = (const float*)d_in[1];
    const float* Wih = (const float*)d_in[2];
    const float* Whh = (const float*)d_in[3];
    const float* bih = (const float*)d_in[4];
    const float* bhh = (const float*)d_in[5];
    const void* srcp = d_in[6];
    const void* dstp = d_in[7];
    float* out       = (float*)d_out;

    int E  = in_sizes[1];
    int Nn = in_sizes[0] / D;
    int n_tiles16 = (Nn + 15) / 16;

    detect_kernel<<<1, 32>>>((const unsigned long long*)srcp,
                             (const unsigned long long*)dstp);

    int n4 = Nn * (D / 4);
    zero_kernel<<<(n4 + 255) / 256, 256>>>(n4);

    prep_kernel<<<32, 256>>>(Wih, Whh, bih, bhh);

    long long total = (long long)E * 16;
    scatter_kernel<<<(int)((total + 255) / 256), 256>>>((const float4*)h, ew,
                                                        srcp, dstp, E);

    cudaFuncSetAttribute(gemm_gru_kernel,
                         cudaFuncAttributeMaxDynamicSharedMemorySize, SM_TOT);
    gemm_gru_kernel<<<148, 256, SM_TOT>>>((const float4*)h, out, Nn, n_tiles16);
}